// round 15
// baseline (speedup 1.0000x reference)
#include <cuda_runtime.h>
#include <cuda_fp16.h>
#include <cstdint>

// ---------------------------------------------------------------------------
// EfficientViT attention block — all three GEMMs on tensor cores (mma.sync
// m16n8k16 fp16), fp32-accuracy via hi/lo split operands where it matters.
//   P1: prep_x  : x -> transposed fp16 hi/lo pairs  g_Xp[b][pix][icpair]
//   P2: prep_w  : BN-scale-folded, split weights g_Wall (qkv) / g_Wpp (proj)
//   K1: qkv_mma : Q/K 3-MMA split; V single-MMA (output is fp16 anyway)
//   K2: attn    : q-tile 128 (32 rows/warp, 2 MMA row-blocks), exp2-domain
//                 softmax, rowsum via ones-MMA, 3-stage cp.async ring
//   K3: proj_mma: out = Wp @ relu(O) + shift, 3-MMA split
// ---------------------------------------------------------------------------

namespace {
constexpr int BATCH = 2;
constexpr int CIN   = 384;
constexpr int NPIX  = 3136;     // 56*56
constexpr int HEADS = 8;
constexpr int KD    = 16;
constexpr int DV    = 64;
constexpr int DH    = 512;
constexpr int OCOUT = 384;
constexpr int BH    = BATCH * HEADS;
constexpr int NT64  = NPIX / 64;             // 49 tiles of 64 (exact)
constexpr int QT128 = (NPIX + 127) / 128;    // 25 pixel tiles of 128
constexpr int ICP   = CIN / 2;               // 192 ic-pairs
constexpr int DHP   = DH / 2;                // 256 ic-pairs for proj
constexpr float EPSBN = 1e-5f;
constexpr float LOG2E = 1.44269504088896341f;

// attn smem ring: 3 stages x (K 64x80B + V 64x144B) = 3 x 14336 = 43008 B
constexpr int STG_BYTES = 64 * 80 + 64 * 144;   // 14336
constexpr int ATTN_SMEM = 3 * STG_BYTES;        // 43008
constexpr uint32_t ONESH2 = 0x3C003C00u;        // f16x2 {1.0, 1.0}

// GEMM W ring: 3 stages x 128 rows x 80 B (10 uint2, 16B-aligned rows)
constexpr int WSTG_BYTES = 128 * 80;            // 10240
}

// scratch (static device arrays: allocation-free per harness rules)
__device__ __align__(16) uint2    g_Xp[BATCH * NPIX * ICP];        // x^T split
__device__ __align__(16) uint2    g_Wall[(256 + DH) * ICP];        // 768 rows q,k,v
__device__ __align__(16) uint2    g_Wpp[OCOUT * DHP];              // proj W
__device__            float       g_shiftAll[768];
__device__            float       g_shiftP[OCOUT];
__device__ __align__(16) uint2    g_Qp[BH * NPIX * 8];             // [bh][pix][perm kdpair]{hi,lo}
__device__ __align__(16) uint2    g_Kp[BH * NPIX * 8];
__device__ __align__(16) uint32_t g_Vh[BH * DV * (NPIX / 2)];      // [bh][d][perm keypair] f16x2
__device__ __align__(16) uint2    g_Oph[BH * NPIX * (DV / 2)];     // relu(O) split [bh][pix][dpair]

// split fp32 pair -> f16x2 hi (v0 low half) + f16x2 lo (residuals)
__device__ __forceinline__ void split2h(float v0, float v1, uint32_t& hi, uint32_t& lo) {
    __half h0 = __float2half_rn(v0), h1 = __float2half_rn(v1);
    hi = ((uint32_t)__half_as_ushort(h1) << 16) | (uint32_t)__half_as_ushort(h0);
    float r0 = v0 - __half2float(h0);
    float r1 = v1 - __half2float(h1);
    asm("cvt.rn.f16x2.f32 %0, %1, %2;" : "=r"(lo) : "f"(r1), "f"(r0));
}
__device__ __forceinline__ uint32_t packh(float v0, float v1) {
    uint32_t d; asm("cvt.rn.f16x2.f32 %0, %1, %2;" : "=r"(d) : "f"(v1), "f"(v0)); return d;
}
__device__ __forceinline__ float ex2(float x) {
    float r; asm("ex2.approx.ftz.f32 %0, %1;" : "=f"(r) : "f"(x)); return r;
}
__device__ __forceinline__ uint32_t smem_u32(const void* p) {
    uint32_t a;
    asm("{ .reg .u64 t; cvta.to.shared.u64 t, %1; cvt.u32.u64 %0, t; }" : "=r"(a) : "l"(p));
    return a;
}
#define CP_ASYNC16(dst, src) \
    asm volatile("cp.async.cg.shared.global [%0], [%1], 16;" :: "r"(dst), "l"(src))
#define CP_COMMIT() asm volatile("cp.async.commit_group;" ::: "memory")
#define CP_WAIT1()  asm volatile("cp.async.wait_group 1;"  ::: "memory")

// mma.sync m16n8k16 fp16 -> f32 accum
// A frag: {(g,t),(g+8,t),(g,t+4),(g+8,t+4)} pair-granularity; B: n=g, kpair=t/t+4;
// C: row=g/g+8, col=2t/2t+1.   (empirically validated rounds 5-14)
__device__ __forceinline__ void mma16816h(float* c, const uint32_t* a, uint32_t b0, uint32_t b1) {
    asm volatile("mma.sync.aligned.m16n8k16.row.col.f32.f16.f16.f32 "
        "{%0,%1,%2,%3}, {%4,%5,%6,%7}, {%8,%9}, {%0,%1,%2,%3};"
        : "+f"(c[0]), "+f"(c[1]), "+f"(c[2]), "+f"(c[3])
        : "r"(a[0]), "r"(a[1]), "r"(a[2]), "r"(a[3]), "r"(b0), "r"(b1));
}

// ---------------------------------------------------------------------------
// P1: transpose + split x. grid (49, 6, 2), block 256. 64 pix x 64 ch per blk.
// ---------------------------------------------------------------------------
__global__ __launch_bounds__(256) void prep_x(const float* __restrict__ x)
{
    __shared__ float s[8][66];
    const int pix0 = blockIdx.x * 64;
    const int cc0  = blockIdx.y * 64;
    const int b    = blockIdx.z;
    const int tid  = threadIdx.x;
    const int lr = tid >> 5, lc = (tid & 31) * 2;
    const int pix = tid >> 2, gp = tid & 3;

    for (int cc = cc0; cc < cc0 + 64; cc += 8) {
        float2 v = *(const float2*)(x + ((size_t)b * CIN + cc + lr) * NPIX + pix0 + lc);
        s[lr][lc] = v.x; s[lr][lc + 1] = v.y;
        __syncthreads();
        uint32_t hi, lo;
        split2h(s[2 * gp][pix], s[2 * gp + 1][pix], hi, lo);
        g_Xp[((size_t)b * NPIX + pix0 + pix) * ICP + (cc >> 1) + gp] = make_uint2(hi, lo);
        __syncthreads();
    }
}

// ---------------------------------------------------------------------------
// P2: fold BN scale into weights, split fp16 hi/lo; compute shifts.
// grid 1152, block 256. rows 0..767 -> g_Wall (q,k,v), 768..1151 -> g_Wpp.
// ---------------------------------------------------------------------------
__global__ __launch_bounds__(256) void prep_w(
    const float* __restrict__ wq, const float* __restrict__ wk,
    const float* __restrict__ wv, const float* __restrict__ wp,
    const float* __restrict__ qg, const float* __restrict__ qb, const float* __restrict__ qm, const float* __restrict__ qv,
    const float* __restrict__ kg, const float* __restrict__ kb, const float* __restrict__ km, const float* __restrict__ kvv,
    const float* __restrict__ vg, const float* __restrict__ vb, const float* __restrict__ vm, const float* __restrict__ vvv,
    const float* __restrict__ pg, const float* __restrict__ pb, const float* __restrict__ pm, const float* __restrict__ pvv)
{
    const int r = blockIdx.x, t = threadIdx.x;
    if (r < 768) {
        const float *w, *gg, *bb, *mm, *vx; int rr;
        if (r < 128)      { w = wq; gg = qg; bb = qb; mm = qm; vx = qv;  rr = r; }
        else if (r < 256) { w = wk; gg = kg; bb = kb; mm = km; vx = kvv; rr = r - 128; }
        else              { w = wv; gg = vg; bb = vb; mm = vm; vx = vvv; rr = r - 256; }
        const float sc = gg[rr] * rsqrtf(vx[rr] + EPSBN);
        if (t == 0) g_shiftAll[r] = bb[rr] - mm[rr] * sc;
        if (t < ICP) {
            float2 w2 = *(const float2*)(w + (size_t)rr * CIN + 2 * t);
            uint32_t hi, lo; split2h(w2.x * sc, w2.y * sc, hi, lo);
            g_Wall[(size_t)r * ICP + t] = make_uint2(hi, lo);
        }
    } else {
        const int rp = r - 768;
        const float sc = pg[rp] * rsqrtf(pvv[rp] + EPSBN);
        if (t == 0) g_shiftP[rp] = pb[rp] - pm[rp] * sc;
        float2 w2 = *(const float2*)(wp + (size_t)rp * DH + 2 * t);
        uint32_t hi, lo; split2h(w2.x * sc, w2.y * sc, hi, lo);
        g_Wpp[(size_t)rp * DHP + t] = make_uint2(hi, lo);
    }
}

// ---------------------------------------------------------------------------
// K1: QKV projection via MMA. grid (25, 6, 2), block 256 (8 warps).
// Block: 128 pixels (M) x 128 out-channels (N), K=384 in 24 steps.
// cp.async 3-stage W ring + A register prefetch; one sync per step.
// by: 0 -> Q (3-MMA split, scaled log2e), 1 -> K (3-MMA split),
// 2..5 -> V (SINGLE MMA: result is quantized to fp16 in g_Vh anyway).
// ---------------------------------------------------------------------------
__global__ __launch_bounds__(256, 2) void qkv_mma()
{
    __shared__ __align__(16) unsigned char sWr[3 * WSTG_BYTES];   // [slot][128 rows x 80B]

    const int by  = blockIdx.y, b = blockIdx.z;
    const int oc0 = by * 128;
    const int pix0 = blockIdx.x * 128;
    const int tid = threadIdx.x;
    const int w   = tid >> 5, lane = tid & 31;
    const int g   = lane >> 2, t = lane & 3;
    const int row0 = pix0 + 16 * w + g;
    const int r0c = min(row0, NPIX - 1), r1c = min(row0 + 8, NPIX - 1);
    const bool isV = (by >= 2);

    const uint2* Xb0 = g_Xp + (size_t)b * NPIX * ICP + (size_t)r0c * ICP;
    const uint2* Xb1 = g_Xp + (size_t)b * NPIX * ICP + (size_t)r1c * ICP;

    const uint32_t smb = smem_u32(sWr);
    const int wrow0 = tid >> 1, wi0 = (tid & 1) * 2;

    auto stage_w = [&](int s, int slot) {
        const uint32_t base = smb + (uint32_t)slot * WSTG_BYTES;
        const uint4* src = (const uint4*)(g_Wall + (size_t)(oc0 + wrow0) * ICP + 8 * s);
        CP_ASYNC16(base + wrow0 * 80 + (wi0    ) * 16, src + wi0    );
        CP_ASYNC16(base + wrow0 * 80 + (wi0 + 1) * 16, src + wi0 + 1);
    };

    float acc[16][4] = {};

    stage_w(0, 0); CP_COMMIT();
    stage_w(1, 1); CP_COMMIT();
    uint2 a0 = Xb0[t], a1 = Xb1[t], a2 = Xb0[t + 4], a3 = Xb1[t + 4];

    int cur = 0, nxt = 2;
    for (int s = 0; s < 24; s++) {
        CP_WAIT1();
        __syncthreads();
        if (s + 2 < 24) stage_w(s + 2, nxt);
        CP_COMMIT();

        uint2 na0, na1, na2, na3;
        if (s + 1 < 24) {
            na0 = Xb0[8 * (s + 1) + t];     na1 = Xb1[8 * (s + 1) + t];
            na2 = Xb0[8 * (s + 1) + t + 4]; na3 = Xb1[8 * (s + 1) + t + 4];
        }

        const uint32_t Ah[4] = {a0.x, a1.x, a2.x, a3.x};
        const uint32_t Al[4] = {a0.y, a1.y, a2.y, a3.y};
        const uint2* sW = (const uint2*)(sWr + cur * WSTG_BYTES);   // stride 10

        if (isV) {
            // V: single hi*hi MMA per n-group (output is fp16-quantized anyway)
            #pragma unroll
            for (int j = 0; j < 16; j++) {
                const uint2 b0 = sW[(8 * j + g) * 10 + t];
                const uint2 b1 = sW[(8 * j + g) * 10 + t + 4];
                mma16816h(acc[j], Ah, b0.x, b1.x);
            }
        } else {
            #pragma unroll
            for (int j = 0; j < 16; j++) {
                const uint2 b0 = sW[(8 * j + g) * 10 + t];
                const uint2 b1 = sW[(8 * j + g) * 10 + t + 4];
                mma16816h(acc[j], Ah, b0.x, b1.x);
                mma16816h(acc[j], Ah, b0.y, b1.y);
                mma16816h(acc[j], Al, b0.x, b1.x);
            }
        }

        a0 = na0; a1 = na1; a2 = na2; a3 = na3;
        cur = (cur == 2) ? 0 : cur + 1;
        nxt = (nxt == 2) ? 0 : nxt + 1;
    }

    if (by < 2) {
        // ---- Q or K: kd-pairs in-lane; PAIR-PERMUTED position so attn's
        // (t, t+4) operands are adjacent: newp = ((kdp&3)<<1)|(kdp>>2).
        // Q additionally pre-scaled by log2e (exp2-domain softmax).
        uint2* QK = (by == 0) ? g_Qp : g_Kp;
        const float qs = (by == 0) ? LOG2E : 1.0f;
        #pragma unroll
        for (int j = 0; j < 16; j++) {
            const int ocl = 8 * j + 2 * t;
            const float s0 = g_shiftAll[oc0 + ocl], s1 = g_shiftAll[oc0 + ocl + 1];
            const int head = ocl >> 4, kdp = (ocl & 15) >> 1;
            const int newp = ((kdp & 3) << 1) | (kdp >> 2);
            uint2* base = QK + ((size_t)(b * HEADS + head) * NPIX) * 8 + newp;
            uint32_t hi, lo;
            if (row0 < NPIX) {
                split2h((acc[j][0] + s0) * qs, (acc[j][1] + s1) * qs, hi, lo);
                base[(size_t)row0 * 8] = make_uint2(hi, lo);
            }
            if (row0 + 8 < NPIX) {
                split2h((acc[j][2] + s0) * qs, (acc[j][3] + s1) * qs, hi, lo);
                base[(size_t)(row0 + 8) * 8] = make_uint2(hi, lo);
            }
        }
    } else {
        // ---- V: pixel-pairs via shfl; PAIR-PERMUTED layout within 32-pair
        // tiles so that attn's PV B-operand (c, c+4) is one LDS.64:
        // newc = (c & 24) | ((c & 3) << 1) | ((c >> 2) & 1)
        #pragma unroll
        for (int j = 0; j < 16; j++) {
            const int ocv = (by - 2) * 128 + 8 * j + 2 * t;
            const float s0 = g_shiftAll[256 + ocv], s1 = g_shiftAll[256 + ocv + 1];
            const int head = ocv >> 6, d = ocv & 63;
            const float v00 = acc[j][0] + s0, v01 = acc[j][1] + s1;
            const float v10 = acc[j][2] + s0, v11 = acc[j][3] + s1;
            const float n00 = __shfl_down_sync(0xffffffffu, v00, 4);
            const float n01 = __shfl_down_sync(0xffffffffu, v01, 4);
            const float n10 = __shfl_down_sync(0xffffffffu, v10, 4);
            const float n11 = __shfl_down_sync(0xffffffffu, v11, 4);
            if (!(g & 1)) {
                uint32_t* vb = g_Vh + ((size_t)(b * HEADS + head) * DV + d) * (NPIX / 2);
                const int pp0 = row0 >> 1, pp1 = (row0 + 8) >> 1;
                const int c0 = pp0 & 31, c1 = pp1 & 31;
                const int q0i = (pp0 & ~31) | (c0 & 24) | ((c0 & 3) << 1) | ((c0 >> 2) & 1);
                const int q1i = (pp1 & ~31) | (c1 & 24) | ((c1 & 3) << 1) | ((c1 >> 2) & 1);
                if (row0 + 1 < NPIX) {
                    vb[q0i] = packh(v00, n00);
                    vb[(NPIX / 2) + q0i] = packh(v01, n01);
                }
                if (row0 + 9 < NPIX) {
                    vb[q1i] = packh(v10, n10);
                    vb[(NPIX / 2) + q1i] = packh(v11, n11);
                }
            }
        }
    }
}

// ---------------------------------------------------------------------------
// K2: attention. grid (25, 16), block 128 (4 warps), q-tile 128.
// Each warp: 32 q-rows as two 16-row MMA blocks sharing the staged K/V tile.
// 3-stage cp.async ring, exp2-domain softmax, rowsum via ones-MMA,
// ballot-gated rescale. Last tile partial -> clamped loads, guarded stores.
// (unchanged from R13)
// ---------------------------------------------------------------------------
__global__ __launch_bounds__(128, 3) void attn_mma_kernel()
{
    extern __shared__ __align__(16) unsigned char smem[];

    const int bh  = blockIdx.y;
    const int q0  = blockIdx.x * 128;
    const int tid = threadIdx.x;
    const int lane = tid & 31;
    const int w   = tid >> 5;
    const int g   = lane >> 2, t = lane & 3;
    const int rowA = q0 + 32 * w + g;            // block A rows: rowA, rowA+8

    // ---- Q fragments for both row blocks (clamped for tail tile) ----
    const uint2* Qp = g_Qp + (size_t)bh * NPIX * 8;
    uint32_t Qhi[2][4], Qlo[2][4];
    #pragma unroll
    for (int bb = 0; bb < 2; bb++) {
        const int r0 = min(rowA + 16 * bb, NPIX - 1);
        const int r1 = min(rowA + 16 * bb + 8, NPIX - 1);
        const uint4 qA = *(const uint4*)(Qp + (size_t)r0 * 8 + 2 * t);
        const uint4 qB = *(const uint4*)(Qp + (size_t)r1 * 8 + 2 * t);
        Qhi[bb][0] = qA.x; Qhi[bb][1] = qB.x; Qhi[bb][2] = qA.z; Qhi[bb][3] = qB.z;
        Qlo[bb][0] = qA.y; Qlo[bb][1] = qB.y; Qlo[bb][2] = qA.w; Qlo[bb][3] = qB.w;
    }

    const uint4* Kp4 = (const uint4*)(g_Kp + (size_t)bh * NPIX * 8);      // 4 uint4 per key
    const uint4* Vp4 = (const uint4*)(g_Vh + (size_t)bh * DV * (NPIX/2)); // 392 uint4 per d-row

    const uint32_t smb = smem_u32(smem);
    const int kR0 = tid >> 2,        kC0 = (tid & 3);
    const int kR1 = (tid + 128) >> 2;
    const int vR[4] = { tid >> 3, (tid + 128) >> 3, (tid + 256) >> 3, (tid + 384) >> 3 };
    const int vC = tid & 7;

    auto stage_tile = [&](int kt, int slot) {
        const uint32_t sb = smb + (uint32_t)slot * STG_BYTES;
        const int kb = kt * 64;
        CP_ASYNC16(sb + kR0 * 80 + kC0 * 16, Kp4 + (size_t)(kb + kR0) * 4 + kC0);
        CP_ASYNC16(sb + kR1 * 80 + kC0 * 16, Kp4 + (size_t)(kb + kR1) * 4 + kC0);
        const uint32_t vb = sb + 5120;
        #pragma unroll
        for (int i = 0; i < 4; i++)
            CP_ASYNC16(vb + vR[i] * 144 + vC * 16, Vp4 + (size_t)vR[i] * 392 + kt * 8 + vC);
    };

    float o[2][8][4] = {};
    float o9[2][4] = {};                 // per-block rowsum accumulators
    float m0[2] = {-3.0e38f, -3.0e38f};
    float m1[2] = {-3.0e38f, -3.0e38f};

    stage_tile(0, 0); CP_COMMIT();
    stage_tile(1, 1); CP_COMMIT();

    int cur = 0, nxt = 2;
    for (int kt = 0; kt < NT64; kt++) {
        CP_WAIT1();
        __syncthreads();
        if (kt + 2 < NT64) stage_tile(kt + 2, nxt);
        CP_COMMIT();

        const unsigned char* stg = smem + cur * STG_BYTES;
        cur = (cur == 2) ? 0 : cur + 1;
        nxt = (nxt == 2) ? 0 : nxt + 1;
        const uint32_t* sV = (const uint32_t*)(stg + 5120);   // stride 36

        #pragma unroll
        for (int bb = 0; bb < 2; bb++) {
            // ---- S = Q K^T : 8 key-groups, 1 LDS.128 + 3 split MMAs each ----
            float s[8][4] = {};
            #pragma unroll
            for (int j = 0; j < 8; j++) {
                const uint4 kv = *(const uint4*)(stg + (8 * j + g) * 80 + t * 16);
                mma16816h(s[j], Qhi[bb], kv.x, kv.z);   // Qh*Kh
                mma16816h(s[j], Qhi[bb], kv.y, kv.w);   // Qh*Kl
                mma16816h(s[j], Qlo[bb], kv.x, kv.z);   // Ql*Kh
            }

            // ---- online max (ballot-gated rescale), log2 domain ----
            float mt0 = s[0][0], mt1 = s[0][2];
            #pragma unroll
            for (int j = 0; j < 8; j++) {
                mt0 = fmaxf(mt0, fmaxf(s[j][0], s[j][1]));
                mt1 = fmaxf(mt1, fmaxf(s[j][2], s[j][3]));
            }
            mt0 = fmaxf(mt0, __shfl_xor_sync(0xffffffffu, mt0, 1));
            mt0 = fmaxf(mt0, __shfl_xor_sync(0xffffffffu, mt0, 2));
            mt1 = fmaxf(mt1, __shfl_xor_sync(0xffffffffu, mt1, 1));
            mt1 = fmaxf(mt1, __shfl_xor_sync(0xffffffffu, mt1, 2));
            const bool chg = (mt0 > m0[bb]) | (mt1 > m1[bb]);
            if (__ballot_sync(0xffffffffu, chg) != 0u) {
                const float mn0 = fmaxf(m0[bb], mt0), mn1 = fmaxf(m1[bb], mt1);
                const float c0 = ex2(m0[bb] - mn0), c1 = ex2(m1[bb] - mn1);
                m0[bb] = mn0; m1[bb] = mn1;
                o9[bb][0] *= c0; o9[bb][1] *= c0; o9[bb][2] *= c1; o9[bb][3] *= c1;
                #pragma unroll
                for (int j = 0; j < 8; j++) {
                    o[bb][j][0] *= c0; o[bb][j][1] *= c0;
                    o[bb][j][2] *= c1; o[bb][j][3] *= c1;
                }
            }

            // ---- P = exp2(S - m); pack; PV + rowsum MMAs ----
            #pragma unroll
            for (int ss = 0; ss < 4; ss++) {
                uint32_t ph[4];
                ph[0] = packh(ex2(s[2*ss  ][0] - m0[bb]), ex2(s[2*ss  ][1] - m0[bb]));
                ph[1] = packh(ex2(s[2*ss  ][2] - m1[bb]), ex2(s[2*ss  ][3] - m1[bb]));
                ph[2] = packh(ex2(s[2*ss+1][0] - m0[bb]), ex2(s[2*ss+1][1] - m0[bb]));
                ph[3] = packh(ex2(s[2*ss+1][2] - m1[bb]), ex2(s[2*ss+1][3] - m1[bb]));
                const int col2 = 8 * ss + 2 * t;
                #pragma unroll
                for (int j = 0; j < 8; j++) {
                    const uint2 vv = *(const uint2*)&sV[(8 * j + g) * 36 + col2];
                    mma16816h(o[bb][j], ph, vv.x, vv.y);
                }
                mma16816h(o9[bb], ph, ONESH2, ONESH2);   // rowsum
            }
        }
    }

    // ---- write relu(O) split pairs: dpair = 4j+t (d = 8j+2t, +1) ----
    #pragma unroll
    for (int bb = 0; bb < 2; bb++) {
        const float inv0 = 1.f / o9[bb][0];
        const float inv1 = 1.f / o9[bb][2];
        const int r0 = rowA + 16 * bb;
        uint32_t hi, lo;
        if (r0 < NPIX) {
            uint2* ob = g_Oph + ((size_t)bh * NPIX + r0) * 32;
            #pragma unroll
            for (int j = 0; j < 8; j++) {
                split2h(fmaxf(o[bb][j][0] * inv0, 0.f), fmaxf(o[bb][j][1] * inv0, 0.f), hi, lo);
                ob[4 * j + t] = make_uint2(hi, lo);
            }
        }
        if (r0 + 8 < NPIX) {
            uint2* ob1 = g_Oph + ((size_t)bh * NPIX + r0 + 8) * 32;
            #pragma unroll
            for (int j = 0; j < 8; j++) {
                split2h(fmaxf(o[bb][j][2] * inv1, 0.f), fmaxf(o[bb][j][3] * inv1, 0.f), hi, lo);
                ob1[4 * j + t] = make_uint2(hi, lo);
            }
        }
    }
}

// ---------------------------------------------------------------------------
// K3: projection via MMA. grid (25, 3, 2), block 256 (8 warps).
// Block: 128 pixels x 128 oc, K=512 in 32 steps. A = relu(O) pairs (g_Oph).
// cp.async 3-stage W ring + A register prefetch; one sync per step.
// ---------------------------------------------------------------------------
__global__ __launch_bounds__(256, 2) void proj_mma(float* __restrict__ out)
{
    __shared__ __align__(16) unsigned char sWr[3 * WSTG_BYTES];

    const int b = blockIdx.z;
    const int oc0 = blockIdx.y * 128;
    const int pix0 = blockIdx.x * 128;
    const int tid = threadIdx.x;
    const int w = tid >> 5, lane = tid & 31;
    const int g = lane >> 2, t = lane & 3;
    const int row0 = pix0 + 16 * w + g;
    const int r0c = min(row0, NPIX - 1), r1c = min(row0 + 8, NPIX - 1);

    const uint32_t smb = smem_u32(sWr);
    const int wrow0 = tid >> 1, wi0 = (tid & 1) * 2;

    auto stage_w = [&](int s, int slot) {
        const uint32_t base = smb + (uint32_t)slot * WSTG_BYTES;
        const uint4* src = (const uint4*)(g_Wpp + (size_t)(oc0 + wrow0) * DHP + 8 * s);
        CP_ASYNC16(base + wrow0 * 80 + (wi0    ) * 16, src + wi0    );
        CP_ASYNC16(base + wrow0 * 80 + (wi0 + 1) * 16, src + wi0 + 1);
    };

    auto load_a = [&](int s, uint2& a0, uint2& a1, uint2& a2, uint2& a3) {
        const int head = s >> 2, dp = 8 * (s & 3) + t;
        const uint2* Ob = g_Oph + ((size_t)(b * HEADS + head) * NPIX) * 32;
        a0 = Ob[(size_t)r0c * 32 + dp];
        a1 = Ob[(size_t)r1c * 32 + dp];
        a2 = Ob[(size_t)r0c * 32 + dp + 4];
        a3 = Ob[(size_t)r1c * 32 + dp + 4];
    };

    float acc[16][4] = {};

    stage_w(0, 0); CP_COMMIT();
    stage_w(1, 1); CP_COMMIT();
    uint2 a0, a1, a2, a3;
    load_a(0, a0, a1, a2, a3);

    int cur = 0, nxt = 2;
    for (int s = 0; s < 32; s++) {
        CP_WAIT1();
        __syncthreads();
        if (s + 2 < 32) stage_w(s + 2, nxt);
        CP_COMMIT();

        uint2 na0, na1, na2, na3;
        if (s + 1 < 32) load_a(s + 1, na0, na1, na2, na3);

        const uint32_t Ah[4] = {a0.x, a1.x, a2.x, a3.x};
        const uint32_t Al[4] = {a0.y, a1.y, a2.y, a3.y};
        const uint2* sW = (const uint2*)(sWr + cur * WSTG_BYTES);   // stride 10

        #pragma unroll
        for (int j = 0; j < 16; j++) {
            const uint2 b0 = sW[(8 * j + g) * 10 + t];
            const uint2 b1 = sW[(8 * j + g) * 10 + t + 4];
            mma16816h(acc[j], Ah, b0.x, b1.x);
            mma16816h(acc[j], Ah, b0.y, b1.y);
            mma16816h(acc[j], Al, b0.x, b1.x);
        }

        a0 = na0; a1 = na1; a2 = na2; a3 = na3;
        cur = (cur == 2) ? 0 : cur + 1;
        nxt = (nxt == 2) ? 0 : nxt + 1;
    }

    #pragma unroll
    for (int j = 0; j < 16; j++) {
        const int oc = oc0 + 8 * j + 2 * t;
        const float s0 = g_shiftP[oc], s1 = g_shiftP[oc + 1];
        float* ob = out + ((size_t)b * OCOUT + oc) * NPIX;
        if (row0 < NPIX) {
            ob[row0] = acc[j][0] + s0;
            ob[NPIX + row0] = acc[j][1] + s1;
        }
        if (row0 + 8 < NPIX) {
            ob[row0 + 8] = acc[j][2] + s0;
            ob[NPIX + row0 + 8] = acc[j][3] + s1;
        }
    }
}

// ---------------------------------------------------------------------------
extern "C" void kernel_launch(void* const* d_in, const int* in_sizes, int n_in,
                              void* d_out, int out_size)
{
    (void)in_sizes; (void)n_in; (void)out_size;
    const float* x   = (const float*)d_in[0];
    const float* wq  = (const float*)d_in[1];
    const float* qg  = (const float*)d_in[2];
    const float* qb  = (const float*)d_in[3];
    const float* qm  = (const float*)d_in[4];
    const float* qv  = (const float*)d_in[5];
    const float* wk  = (const float*)d_in[6];
    const float* kg  = (const float*)d_in[7];
    const float* kb  = (const float*)d_in[8];
    const float* km  = (const float*)d_in[9];
    const float* kvv = (const float*)d_in[10];
    const float* wv  = (const float*)d_in[11];
    const float* vg  = (const float*)d_in[12];
    const float* vb  = (const float*)d_in[13];
    const float* vm  = (const float*)d_in[14];
    const float* vvv = (const float*)d_in[15];
    const float* wp  = (const float*)d_in[16];
    const float* pg  = (const float*)d_in[17];
    const float* pb  = (const float*)d_in[18];
    const float* pm  = (const float*)d_in[19];
    const float* pvv = (const float*)d_in[20];
    float* out = (float*)d_out;

    cudaFuncSetAttribute(attn_mma_kernel, cudaFuncAttributeMaxDynamicSharedMemorySize, ATTN_SMEM);

    prep_x<<<dim3(NT64, 6, BATCH), 256>>>(x);
    prep_w<<<dim3(1152), 256>>>(wq, wk, wv, wp,
                                qg, qb, qm, qv,
                                kg, kb, km, kvv,
                                vg, vb, vm, vvv,
                                pg, pb, pm, pvv);
    qkv_mma<<<dim3(QT128, 6, BATCH), 256>>>();
    attn_mma_kernel<<<dim3(QT128, BH), 128, ATTN_SMEM>>>();
    proj_mma<<<dim3(QT128, 3, BATCH), 256>>>(out);
}

// round 16
// speedup vs baseline: 1.0475x; 1.0475x over previous
#include <cuda_runtime.h>
#include <cuda_fp16.h>
#include <cstdint>

// ---------------------------------------------------------------------------
// EfficientViT attention block — all three GEMMs on tensor cores (mma.sync
// m16n8k16 fp16), fp32-accuracy via hi/lo split operands (3-MMA products).
//   P1: prep_x  : x -> transposed fp16 hi/lo pairs  g_Xp[b][pix][icpair]
//   P2: prep_w  : BN-scale-folded, split, PAIR-PERMUTED weights
//   K1: qkv_mma : Q/K/V 3-MMA split; W B-operands via single LDS.128
//   K2: attn    : q-tile 128 (32 rows/warp, 2 MMA row-blocks), exp2-domain
//                 softmax, rowsum via ones-MMA, 3-stage cp.async ring
//   K3: proj_mma: out = Wp @ relu(O) + shift; W B-operands via LDS.128
// ---------------------------------------------------------------------------

namespace {
constexpr int BATCH = 2;
constexpr int CIN   = 384;
constexpr int NPIX  = 3136;     // 56*56
constexpr int HEADS = 8;
constexpr int KD    = 16;
constexpr int DV    = 64;
constexpr int DH    = 512;
constexpr int OCOUT = 384;
constexpr int BH    = BATCH * HEADS;
constexpr int NT64  = NPIX / 64;             // 49 tiles of 64 (exact)
constexpr int QT128 = (NPIX + 127) / 128;    // 25 pixel tiles of 128
constexpr int ICP   = CIN / 2;               // 192 ic-pairs
constexpr int DHP   = DH / 2;                // 256 ic-pairs for proj
constexpr float EPSBN = 1e-5f;
constexpr float LOG2E = 1.44269504088896341f;

// attn smem ring: 3 stages x (K 64x80B + V 64x144B) = 3 x 14336 = 43008 B
constexpr int STG_BYTES = 64 * 80 + 64 * 144;   // 14336
constexpr int ATTN_SMEM = 3 * STG_BYTES;        // 43008
constexpr uint32_t ONESH2 = 0x3C003C00u;        // f16x2 {1.0, 1.0}

// GEMM W ring: 3 stages x 128 rows x 80 B (10 uint2, 16B-aligned rows)
constexpr int WSTG_BYTES = 128 * 80;            // 10240
}

// scratch (static device arrays: allocation-free per harness rules)
__device__ __align__(16) uint2    g_Xp[BATCH * NPIX * ICP];        // x^T split
__device__ __align__(16) uint2    g_Wall[(256 + DH) * ICP];        // 768 rows q,k,v (perm pairs)
__device__ __align__(16) uint2    g_Wpp[OCOUT * DHP];              // proj W (perm pairs)
__device__            float       g_shiftAll[768];
__device__            float       g_shiftP[OCOUT];
__device__ __align__(16) uint2    g_Qp[BH * NPIX * 8];             // [bh][pix][perm kdpair]{hi,lo}
__device__ __align__(16) uint2    g_Kp[BH * NPIX * 8];
__device__ __align__(16) uint32_t g_Vh[BH * DV * (NPIX / 2)];      // [bh][d][perm keypair] f16x2
__device__ __align__(16) uint2    g_Oph[BH * NPIX * (DV / 2)];     // relu(O) split [bh][pix][dpair]

// split fp32 pair -> f16x2 hi (v0 low half) + f16x2 lo (residuals)
__device__ __forceinline__ void split2h(float v0, float v1, uint32_t& hi, uint32_t& lo) {
    __half h0 = __float2half_rn(v0), h1 = __float2half_rn(v1);
    hi = ((uint32_t)__half_as_ushort(h1) << 16) | (uint32_t)__half_as_ushort(h0);
    float r0 = v0 - __half2float(h0);
    float r1 = v1 - __half2float(h1);
    asm("cvt.rn.f16x2.f32 %0, %1, %2;" : "=r"(lo) : "f"(r1), "f"(r0));
}
__device__ __forceinline__ uint32_t packh(float v0, float v1) {
    uint32_t d; asm("cvt.rn.f16x2.f32 %0, %1, %2;" : "=r"(d) : "f"(v1), "f"(v0)); return d;
}
__device__ __forceinline__ float ex2(float x) {
    float r; asm("ex2.approx.ftz.f32 %0, %1;" : "=f"(r) : "f"(x)); return r;
}
__device__ __forceinline__ uint32_t smem_u32(const void* p) {
    uint32_t a;
    asm("{ .reg .u64 t; cvta.to.shared.u64 t, %1; cvt.u32.u64 %0, t; }" : "=r"(a) : "l"(p));
    return a;
}
#define CP_ASYNC16(dst, src) \
    asm volatile("cp.async.cg.shared.global [%0], [%1], 16;" :: "r"(dst), "l"(src))
#define CP_COMMIT() asm volatile("cp.async.commit_group;" ::: "memory")
#define CP_WAIT1()  asm volatile("cp.async.wait_group 1;"  ::: "memory")

// mma.sync m16n8k16 fp16 -> f32 accum
// A frag: {(g,t),(g+8,t),(g,t+4),(g+8,t+4)} pair-granularity; B: n=g, kpair=t/t+4;
// C: row=g/g+8, col=2t/2t+1.   (empirically validated rounds 5-15)
__device__ __forceinline__ void mma16816h(float* c, const uint32_t* a, uint32_t b0, uint32_t b1) {
    asm volatile("mma.sync.aligned.m16n8k16.row.col.f32.f16.f16.f32 "
        "{%0,%1,%2,%3}, {%4,%5,%6,%7}, {%8,%9}, {%0,%1,%2,%3};"
        : "+f"(c[0]), "+f"(c[1]), "+f"(c[2]), "+f"(c[3])
        : "r"(a[0]), "r"(a[1]), "r"(a[2]), "r"(a[3]), "r"(b0), "r"(b1));
}

// ---------------------------------------------------------------------------
// P1: transpose + split x. grid (49, 6, 2), block 256. 64 pix x 64 ch per blk.
// ---------------------------------------------------------------------------
__global__ __launch_bounds__(256) void prep_x(const float* __restrict__ x)
{
    __shared__ float s[8][66];
    const int pix0 = blockIdx.x * 64;
    const int cc0  = blockIdx.y * 64;
    const int b    = blockIdx.z;
    const int tid  = threadIdx.x;
    const int lr = tid >> 5, lc = (tid & 31) * 2;
    const int pix = tid >> 2, gp = tid & 3;

    for (int cc = cc0; cc < cc0 + 64; cc += 8) {
        float2 v = *(const float2*)(x + ((size_t)b * CIN + cc + lr) * NPIX + pix0 + lc);
        s[lr][lc] = v.x; s[lr][lc + 1] = v.y;
        __syncthreads();
        uint32_t hi, lo;
        split2h(s[2 * gp][pix], s[2 * gp + 1][pix], hi, lo);
        g_Xp[((size_t)b * NPIX + pix0 + pix) * ICP + (cc >> 1) + gp] = make_uint2(hi, lo);
        __syncthreads();
    }
}

// ---------------------------------------------------------------------------
// P2: fold BN scale into weights, split fp16 hi/lo; PAIR-PERMUTE within each
// 8-pair group (p -> ((p&3)<<1)|(p>>2)) so GEMM B-operands (t, t+4) are one
// LDS.128. Compute shifts. grid 1152, block 256.
// ---------------------------------------------------------------------------
__global__ __launch_bounds__(256) void prep_w(
    const float* __restrict__ wq, const float* __restrict__ wk,
    const float* __restrict__ wv, const float* __restrict__ wp,
    const float* __restrict__ qg, const float* __restrict__ qb, const float* __restrict__ qm, const float* __restrict__ qv,
    const float* __restrict__ kg, const float* __restrict__ kb, const float* __restrict__ km, const float* __restrict__ kvv,
    const float* __restrict__ vg, const float* __restrict__ vb, const float* __restrict__ vm, const float* __restrict__ vvv,
    const float* __restrict__ pg, const float* __restrict__ pb, const float* __restrict__ pm, const float* __restrict__ pvv)
{
    const int r = blockIdx.x, t = threadIdx.x;
    const int w8 = t & 7;
    const int tperm = (t & ~7) | (((w8 & 3) << 1) | (w8 >> 2));
    if (r < 768) {
        const float *w, *gg, *bb, *mm, *vx; int rr;
        if (r < 128)      { w = wq; gg = qg; bb = qb; mm = qm; vx = qv;  rr = r; }
        else if (r < 256) { w = wk; gg = kg; bb = kb; mm = km; vx = kvv; rr = r - 128; }
        else              { w = wv; gg = vg; bb = vb; mm = vm; vx = vvv; rr = r - 256; }
        const float sc = gg[rr] * rsqrtf(vx[rr] + EPSBN);
        if (t == 0) g_shiftAll[r] = bb[rr] - mm[rr] * sc;
        if (t < ICP) {
            float2 w2 = *(const float2*)(w + (size_t)rr * CIN + 2 * t);
            uint32_t hi, lo; split2h(w2.x * sc, w2.y * sc, hi, lo);
            g_Wall[(size_t)r * ICP + tperm] = make_uint2(hi, lo);
        }
    } else {
        const int rp = r - 768;
        const float sc = pg[rp] * rsqrtf(pvv[rp] + EPSBN);
        if (t == 0) g_shiftP[rp] = pb[rp] - pm[rp] * sc;
        float2 w2 = *(const float2*)(wp + (size_t)rp * DH + 2 * t);
        uint32_t hi, lo; split2h(w2.x * sc, w2.y * sc, hi, lo);
        g_Wpp[(size_t)rp * DHP + tperm] = make_uint2(hi, lo);
    }
}

// ---------------------------------------------------------------------------
// K1: QKV projection via MMA. grid (25, 6, 2), block 256 (8 warps).
// Block: 128 pixels (M) x 128 out-channels (N), K=384 in 24 steps.
// cp.async 3-stage W ring + A register prefetch; one sync per step.
// W pair-permuted: B operands (t, t+4) = one LDS.128.
// by: 0 -> Q (scaled log2e), 1 -> K, 2..5 -> V. All 3-MMA split.
// ---------------------------------------------------------------------------
__global__ __launch_bounds__(256, 2) void qkv_mma()
{
    __shared__ __align__(16) unsigned char sWr[3 * WSTG_BYTES];   // [slot][128 rows x 80B]

    const int by  = blockIdx.y, b = blockIdx.z;
    const int oc0 = by * 128;
    const int pix0 = blockIdx.x * 128;
    const int tid = threadIdx.x;
    const int w   = tid >> 5, lane = tid & 31;
    const int g   = lane >> 2, t = lane & 3;
    const int row0 = pix0 + 16 * w + g;
    const int r0c = min(row0, NPIX - 1), r1c = min(row0 + 8, NPIX - 1);

    const uint2* Xb0 = g_Xp + (size_t)b * NPIX * ICP + (size_t)r0c * ICP;
    const uint2* Xb1 = g_Xp + (size_t)b * NPIX * ICP + (size_t)r1c * ICP;

    const uint32_t smb = smem_u32(sWr);
    const int wrow0 = tid >> 1, wi0 = (tid & 1) * 2;

    auto stage_w = [&](int s, int slot) {
        const uint32_t base = smb + (uint32_t)slot * WSTG_BYTES;
        const uint4* src = (const uint4*)(g_Wall + (size_t)(oc0 + wrow0) * ICP + 8 * s);
        CP_ASYNC16(base + wrow0 * 80 + (wi0    ) * 16, src + wi0    );
        CP_ASYNC16(base + wrow0 * 80 + (wi0 + 1) * 16, src + wi0 + 1);
    };

    float acc[16][4] = {};

    stage_w(0, 0); CP_COMMIT();
    stage_w(1, 1); CP_COMMIT();
    uint2 a0 = Xb0[t], a1 = Xb1[t], a2 = Xb0[t + 4], a3 = Xb1[t + 4];

    int cur = 0, nxt = 2;
    for (int s = 0; s < 24; s++) {
        CP_WAIT1();
        __syncthreads();
        if (s + 2 < 24) stage_w(s + 2, nxt);
        CP_COMMIT();

        uint2 na0, na1, na2, na3;
        if (s + 1 < 24) {
            na0 = Xb0[8 * (s + 1) + t];     na1 = Xb1[8 * (s + 1) + t];
            na2 = Xb0[8 * (s + 1) + t + 4]; na3 = Xb1[8 * (s + 1) + t + 4];
        }

        const uint32_t Ah[4] = {a0.x, a1.x, a2.x, a3.x};
        const uint32_t Al[4] = {a0.y, a1.y, a2.y, a3.y};
        const unsigned char* sWb = sWr + cur * WSTG_BYTES;

        #pragma unroll
        for (int j = 0; j < 16; j++) {
            const uint4 wv4 = *(const uint4*)(sWb + (8 * j + g) * 80 + t * 16);
            mma16816h(acc[j], Ah, wv4.x, wv4.z);   // Ah*Wh
            mma16816h(acc[j], Ah, wv4.y, wv4.w);   // Ah*Wl
            mma16816h(acc[j], Al, wv4.x, wv4.z);   // Al*Wh
        }

        a0 = na0; a1 = na1; a2 = na2; a3 = na3;
        cur = (cur == 2) ? 0 : cur + 1;
        nxt = (nxt == 2) ? 0 : nxt + 1;
    }

    if (by < 2) {
        // ---- Q or K: kd-pairs in-lane; PAIR-PERMUTED position so attn's
        // (t, t+4) operands are adjacent: newp = ((kdp&3)<<1)|(kdp>>2).
        // Q additionally pre-scaled by log2e (exp2-domain softmax).
        uint2* QK = (by == 0) ? g_Qp : g_Kp;
        const float qs = (by == 0) ? LOG2E : 1.0f;
        #pragma unroll
        for (int j = 0; j < 16; j++) {
            const int ocl = 8 * j + 2 * t;
            const float s0 = g_shiftAll[oc0 + ocl], s1 = g_shiftAll[oc0 + ocl + 1];
            const int head = ocl >> 4, kdp = (ocl & 15) >> 1;
            const int newp = ((kdp & 3) << 1) | (kdp >> 2);
            uint2* base = QK + ((size_t)(b * HEADS + head) * NPIX) * 8 + newp;
            uint32_t hi, lo;
            if (row0 < NPIX) {
                split2h((acc[j][0] + s0) * qs, (acc[j][1] + s1) * qs, hi, lo);
                base[(size_t)row0 * 8] = make_uint2(hi, lo);
            }
            if (row0 + 8 < NPIX) {
                split2h((acc[j][2] + s0) * qs, (acc[j][3] + s1) * qs, hi, lo);
                base[(size_t)(row0 + 8) * 8] = make_uint2(hi, lo);
            }
        }
    } else {
        // ---- V: pixel-pairs via shfl; PAIR-PERMUTED layout within 32-pair
        // tiles so that attn's PV B-operand (c, c+4) is one LDS.64:
        // newc = (c & 24) | ((c & 3) << 1) | ((c >> 2) & 1)
        #pragma unroll
        for (int j = 0; j < 16; j++) {
            const int ocv = (by - 2) * 128 + 8 * j + 2 * t;
            const float s0 = g_shiftAll[256 + ocv], s1 = g_shiftAll[256 + ocv + 1];
            const int head = ocv >> 6, d = ocv & 63;
            const float v00 = acc[j][0] + s0, v01 = acc[j][1] + s1;
            const float v10 = acc[j][2] + s0, v11 = acc[j][3] + s1;
            const float n00 = __shfl_down_sync(0xffffffffu, v00, 4);
            const float n01 = __shfl_down_sync(0xffffffffu, v01, 4);
            const float n10 = __shfl_down_sync(0xffffffffu, v10, 4);
            const float n11 = __shfl_down_sync(0xffffffffu, v11, 4);
            if (!(g & 1)) {
                uint32_t* vb = g_Vh + ((size_t)(b * HEADS + head) * DV + d) * (NPIX / 2);
                const int pp0 = row0 >> 1, pp1 = (row0 + 8) >> 1;
                const int c0 = pp0 & 31, c1 = pp1 & 31;
                const int q0i = (pp0 & ~31) | (c0 & 24) | ((c0 & 3) << 1) | ((c0 >> 2) & 1);
                const int q1i = (pp1 & ~31) | (c1 & 24) | ((c1 & 3) << 1) | ((c1 >> 2) & 1);
                if (row0 + 1 < NPIX) {
                    vb[q0i] = packh(v00, n00);
                    vb[(NPIX / 2) + q0i] = packh(v01, n01);
                }
                if (row0 + 9 < NPIX) {
                    vb[q1i] = packh(v10, n10);
                    vb[(NPIX / 2) + q1i] = packh(v11, n11);
                }
            }
        }
    }
}

// ---------------------------------------------------------------------------
// K2: attention. grid (25, 16), block 128 (4 warps), q-tile 128.
// Each warp: 32 q-rows as two 16-row MMA blocks sharing the staged K/V tile.
// 3-stage cp.async ring, exp2-domain softmax, rowsum via ones-MMA,
// ballot-gated rescale. Last tile partial -> clamped loads, guarded stores.
// (unchanged from R13)
// ---------------------------------------------------------------------------
__global__ __launch_bounds__(128, 3) void attn_mma_kernel()
{
    extern __shared__ __align__(16) unsigned char smem[];

    const int bh  = blockIdx.y;
    const int q0  = blockIdx.x * 128;
    const int tid = threadIdx.x;
    const int lane = tid & 31;
    const int w   = tid >> 5;
    const int g   = lane >> 2, t = lane & 3;
    const int rowA = q0 + 32 * w + g;            // block A rows: rowA, rowA+8

    // ---- Q fragments for both row blocks (clamped for tail tile) ----
    const uint2* Qp = g_Qp + (size_t)bh * NPIX * 8;
    uint32_t Qhi[2][4], Qlo[2][4];
    #pragma unroll
    for (int bb = 0; bb < 2; bb++) {
        const int r0 = min(rowA + 16 * bb, NPIX - 1);
        const int r1 = min(rowA + 16 * bb + 8, NPIX - 1);
        const uint4 qA = *(const uint4*)(Qp + (size_t)r0 * 8 + 2 * t);
        const uint4 qB = *(const uint4*)(Qp + (size_t)r1 * 8 + 2 * t);
        Qhi[bb][0] = qA.x; Qhi[bb][1] = qB.x; Qhi[bb][2] = qA.z; Qhi[bb][3] = qB.z;
        Qlo[bb][0] = qA.y; Qlo[bb][1] = qB.y; Qlo[bb][2] = qA.w; Qlo[bb][3] = qB.w;
    }

    const uint4* Kp4 = (const uint4*)(g_Kp + (size_t)bh * NPIX * 8);      // 4 uint4 per key
    const uint4* Vp4 = (const uint4*)(g_Vh + (size_t)bh * DV * (NPIX/2)); // 392 uint4 per d-row

    const uint32_t smb = smem_u32(smem);
    const int kR0 = tid >> 2,        kC0 = (tid & 3);
    const int kR1 = (tid + 128) >> 2;
    const int vR[4] = { tid >> 3, (tid + 128) >> 3, (tid + 256) >> 3, (tid + 384) >> 3 };
    const int vC = tid & 7;

    auto stage_tile = [&](int kt, int slot) {
        const uint32_t sb = smb + (uint32_t)slot * STG_BYTES;
        const int kb = kt * 64;
        CP_ASYNC16(sb + kR0 * 80 + kC0 * 16, Kp4 + (size_t)(kb + kR0) * 4 + kC0);
        CP_ASYNC16(sb + kR1 * 80 + kC0 * 16, Kp4 + (size_t)(kb + kR1) * 4 + kC0);
        const uint32_t vb = sb + 5120;
        #pragma unroll
        for (int i = 0; i < 4; i++)
            CP_ASYNC16(vb + vR[i] * 144 + vC * 16, Vp4 + (size_t)vR[i] * 392 + kt * 8 + vC);
    };

    float o[2][8][4] = {};
    float o9[2][4] = {};                 // per-block rowsum accumulators
    float m0[2] = {-3.0e38f, -3.0e38f};
    float m1[2] = {-3.0e38f, -3.0e38f};

    stage_tile(0, 0); CP_COMMIT();
    stage_tile(1, 1); CP_COMMIT();

    int cur = 0, nxt = 2;
    for (int kt = 0; kt < NT64; kt++) {
        CP_WAIT1();
        __syncthreads();
        if (kt + 2 < NT64) stage_tile(kt + 2, nxt);
        CP_COMMIT();

        const unsigned char* stg = smem + cur * STG_BYTES;
        cur = (cur == 2) ? 0 : cur + 1;
        nxt = (nxt == 2) ? 0 : nxt + 1;
        const uint32_t* sV = (const uint32_t*)(stg + 5120);   // stride 36

        #pragma unroll
        for (int bb = 0; bb < 2; bb++) {
            // ---- S = Q K^T : 8 key-groups, 1 LDS.128 + 3 split MMAs each ----
            float s[8][4] = {};
            #pragma unroll
            for (int j = 0; j < 8; j++) {
                const uint4 kv = *(const uint4*)(stg + (8 * j + g) * 80 + t * 16);
                mma16816h(s[j], Qhi[bb], kv.x, kv.z);   // Qh*Kh
                mma16816h(s[j], Qhi[bb], kv.y, kv.w);   // Qh*Kl
                mma16816h(s[j], Qlo[bb], kv.x, kv.z);   // Ql*Kh
            }

            // ---- online max (ballot-gated rescale), log2 domain ----
            float mt0 = s[0][0], mt1 = s[0][2];
            #pragma unroll
            for (int j = 0; j < 8; j++) {
                mt0 = fmaxf(mt0, fmaxf(s[j][0], s[j][1]));
                mt1 = fmaxf(mt1, fmaxf(s[j][2], s[j][3]));
            }
            mt0 = fmaxf(mt0, __shfl_xor_sync(0xffffffffu, mt0, 1));
            mt0 = fmaxf(mt0, __shfl_xor_sync(0xffffffffu, mt0, 2));
            mt1 = fmaxf(mt1, __shfl_xor_sync(0xffffffffu, mt1, 1));
            mt1 = fmaxf(mt1, __shfl_xor_sync(0xffffffffu, mt1, 2));
            const bool chg = (mt0 > m0[bb]) | (mt1 > m1[bb]);
            if (__ballot_sync(0xffffffffu, chg) != 0u) {
                const float mn0 = fmaxf(m0[bb], mt0), mn1 = fmaxf(m1[bb], mt1);
                const float c0 = ex2(m0[bb] - mn0), c1 = ex2(m1[bb] - mn1);
                m0[bb] = mn0; m1[bb] = mn1;
                o9[bb][0] *= c0; o9[bb][1] *= c0; o9[bb][2] *= c1; o9[bb][3] *= c1;
                #pragma unroll
                for (int j = 0; j < 8; j++) {
                    o[bb][j][0] *= c0; o[bb][j][1] *= c0;
                    o[bb][j][2] *= c1; o[bb][j][3] *= c1;
                }
            }

            // ---- P = exp2(S - m); pack; PV + rowsum MMAs ----
            #pragma unroll
            for (int ss = 0; ss < 4; ss++) {
                uint32_t ph[4];
                ph[0] = packh(ex2(s[2*ss  ][0] - m0[bb]), ex2(s[2*ss  ][1] - m0[bb]));
                ph[1] = packh(ex2(s[2*ss  ][2] - m1[bb]), ex2(s[2*ss  ][3] - m1[bb]));
                ph[2] = packh(ex2(s[2*ss+1][0] - m0[bb]), ex2(s[2*ss+1][1] - m0[bb]));
                ph[3] = packh(ex2(s[2*ss+1][2] - m1[bb]), ex2(s[2*ss+1][3] - m1[bb]));
                const int col2 = 8 * ss + 2 * t;
                #pragma unroll
                for (int j = 0; j < 8; j++) {
                    const uint2 vv = *(const uint2*)&sV[(8 * j + g) * 36 + col2];
                    mma16816h(o[bb][j], ph, vv.x, vv.y);
                }
                mma16816h(o9[bb], ph, ONESH2, ONESH2);   // rowsum
            }
        }
    }

    // ---- write relu(O) split pairs: dpair = 4j+t (d = 8j+2t, +1) ----
    #pragma unroll
    for (int bb = 0; bb < 2; bb++) {
        const float inv0 = 1.f / o9[bb][0];
        const float inv1 = 1.f / o9[bb][2];
        const int r0 = rowA + 16 * bb;
        uint32_t hi, lo;
        if (r0 < NPIX) {
            uint2* ob = g_Oph + ((size_t)bh * NPIX + r0) * 32;
            #pragma unroll
            for (int j = 0; j < 8; j++) {
                split2h(fmaxf(o[bb][j][0] * inv0, 0.f), fmaxf(o[bb][j][1] * inv0, 0.f), hi, lo);
                ob[4 * j + t] = make_uint2(hi, lo);
            }
        }
        if (r0 + 8 < NPIX) {
            uint2* ob1 = g_Oph + ((size_t)bh * NPIX + r0 + 8) * 32;
            #pragma unroll
            for (int j = 0; j < 8; j++) {
                split2h(fmaxf(o[bb][j][2] * inv1, 0.f), fmaxf(o[bb][j][3] * inv1, 0.f), hi, lo);
                ob1[4 * j + t] = make_uint2(hi, lo);
            }
        }
    }
}

// ---------------------------------------------------------------------------
// K3: projection via MMA. grid (25, 3, 2), block 256 (8 warps).
// Block: 128 pixels x 128 oc, K=512 in 32 steps. A = relu(O) pairs (g_Oph).
// cp.async 3-stage W ring + A register prefetch; one sync per step.
// W pair-permuted: B operands (t, t+4) = one LDS.128.
// ---------------------------------------------------------------------------
__global__ __launch_bounds__(256, 2) void proj_mma(float* __restrict__ out)
{
    __shared__ __align__(16) unsigned char sWr[3 * WSTG_BYTES];

    const int b = blockIdx.z;
    const int oc0 = blockIdx.y * 128;
    const int pix0 = blockIdx.x * 128;
    const int tid = threadIdx.x;
    const int w = tid >> 5, lane = tid & 31;
    const int g = lane >> 2, t = lane & 3;
    const int row0 = pix0 + 16 * w + g;
    const int r0c = min(row0, NPIX - 1), r1c = min(row0 + 8, NPIX - 1);

    const uint32_t smb = smem_u32(sWr);
    const int wrow0 = tid >> 1, wi0 = (tid & 1) * 2;

    auto stage_w = [&](int s, int slot) {
        const uint32_t base = smb + (uint32_t)slot * WSTG_BYTES;
        const uint4* src = (const uint4*)(g_Wpp + (size_t)(oc0 + wrow0) * DHP + 8 * s);
        CP_ASYNC16(base + wrow0 * 80 + (wi0    ) * 16, src + wi0    );
        CP_ASYNC16(base + wrow0 * 80 + (wi0 + 1) * 16, src + wi0 + 1);
    };

    auto load_a = [&](int s, uint2& a0, uint2& a1, uint2& a2, uint2& a3) {
        const int head = s >> 2, dp = 8 * (s & 3) + t;
        const uint2* Ob = g_Oph + ((size_t)(b * HEADS + head) * NPIX) * 32;
        a0 = Ob[(size_t)r0c * 32 + dp];
        a1 = Ob[(size_t)r1c * 32 + dp];
        a2 = Ob[(size_t)r0c * 32 + dp + 4];
        a3 = Ob[(size_t)r1c * 32 + dp + 4];
    };

    float acc[16][4] = {};

    stage_w(0, 0); CP_COMMIT();
    stage_w(1, 1); CP_COMMIT();
    uint2 a0, a1, a2, a3;
    load_a(0, a0, a1, a2, a3);

    int cur = 0, nxt = 2;
    for (int s = 0; s < 32; s++) {
        CP_WAIT1();
        __syncthreads();
        if (s + 2 < 32) stage_w(s + 2, nxt);
        CP_COMMIT();

        uint2 na0, na1, na2, na3;
        if (s + 1 < 32) load_a(s + 1, na0, na1, na2, na3);

        const uint32_t Ah[4] = {a0.x, a1.x, a2.x, a3.x};
        const uint32_t Al[4] = {a0.y, a1.y, a2.y, a3.y};
        const unsigned char* sWb = sWr + cur * WSTG_BYTES;

        #pragma unroll
        for (int j = 0; j < 16; j++) {
            const uint4 wv4 = *(const uint4*)(sWb + (8 * j + g) * 80 + t * 16);
            mma16816h(acc[j], Ah, wv4.x, wv4.z);
            mma16816h(acc[j], Ah, wv4.y, wv4.w);
            mma16816h(acc[j], Al, wv4.x, wv4.z);
        }

        a0 = na0; a1 = na1; a2 = na2; a3 = na3;
        cur = (cur == 2) ? 0 : cur + 1;
        nxt = (nxt == 2) ? 0 : nxt + 1;
    }

    #pragma unroll
    for (int j = 0; j < 16; j++) {
        const int oc = oc0 + 8 * j + 2 * t;
        const float s0 = g_shiftP[oc], s1 = g_shiftP[oc + 1];
        float* ob = out + ((size_t)b * OCOUT + oc) * NPIX;
        if (row0 < NPIX) {
            ob[row0] = acc[j][0] + s0;
            ob[NPIX + row0] = acc[j][1] + s1;
        }
        if (row0 + 8 < NPIX) {
            ob[row0 + 8] = acc[j][2] + s0;
            ob[NPIX + row0 + 8] = acc[j][3] + s1;
        }
    }
}

// ---------------------------------------------------------------------------
extern "C" void kernel_launch(void* const* d_in, const int* in_sizes, int n_in,
                              void* d_out, int out_size)
{
    (void)in_sizes; (void)n_in; (void)out_size;
    const float* x   = (const float*)d_in[0];
    const float* wq  = (const float*)d_in[1];
    const float* qg  = (const float*)d_in[2];
    const float* qb  = (const float*)d_in[3];
    const float* qm  = (const float*)d_in[4];
    const float* qv  = (const float*)d_in[5];
    const float* wk  = (const float*)d_in[6];
    const float* kg  = (const float*)d_in[7];
    const float* kb  = (const float*)d_in[8];
    const float* km  = (const float*)d_in[9];
    const float* kvv = (const float*)d_in[10];
    const float* wv  = (const float*)d_in[11];
    const float* vg  = (const float*)d_in[12];
    const float* vb  = (const float*)d_in[13];
    const float* vm  = (const float*)d_in[14];
    const float* vvv = (const float*)d_in[15];
    const float* wp  = (const float*)d_in[16];
    const float* pg  = (const float*)d_in[17];
    const float* pb  = (const float*)d_in[18];
    const float* pm  = (const float*)d_in[19];
    const float* pvv = (const float*)d_in[20];
    float* out = (float*)d_out;

    cudaFuncSetAttribute(attn_mma_kernel, cudaFuncAttributeMaxDynamicSharedMemorySize, ATTN_SMEM);

    prep_x<<<dim3(NT64, 6, BATCH), 256>>>(x);
    prep_w<<<dim3(1152), 256>>>(wq, wk, wv, wp,
                                qg, qb, qm, qv,
                                kg, kb, km, kvv,
                                vg, vb, vm, vvv,
                                pg, pb, pm, pvv);
    qkv_mma<<<dim3(QT128, 6, BATCH), 256>>>();
    attn_mma_kernel<<<dim3(QT128, BH), 128, ATTN_SMEM>>>();
    proj_mma<<<dim3(QT128, 3, BATCH), 256>>>(out);
}